// round 2
// baseline (speedup 1.0000x reference)
#include <cuda_runtime.h>
#include <cstdint>
#include <cstddef>

#define EPSV 1e-5f
#define MM 8192
#define KK 2048
#define NN 2048

// ---------------- scratch (device globals: no runtime allocation) ----------------
__device__ int8_t g_qx[(size_t)MM * KK];   // 16 MB quantized activations
__device__ int8_t g_qw[(size_t)NN * KK];   // 4 MB ternary weights
__device__ float g_rowscale[MM];
__device__ float g_partial[1024];
__device__ float g_scale;

// ---------------- helpers ----------------
__device__ __forceinline__ uint32_t smem_u32(const void* p) {
    uint32_t a;
    asm("{ .reg .u64 t; cvta.to.shared.u64 t, %1; cvt.u32.u64 %0, t; }" : "=r"(a) : "l"(p));
    return a;
}

__device__ __forceinline__ void cp16(uint32_t dst, const void* src) {
    asm volatile("cp.async.cg.shared.global [%0], [%1], 16;" :: "r"(dst), "l"(src) : "memory");
}

__device__ __forceinline__ uint32_t lds32(uint32_t addr) {
    uint32_t v;
    asm volatile("ld.shared.b32 %0, [%1];" : "=r"(v) : "r"(addr));
    return v;
}

__device__ __forceinline__ void mma_s8(int* c, const uint32_t* a, const uint32_t* b) {
    asm volatile(
        "mma.sync.aligned.m16n8k32.row.col.s32.s8.s8.s32 "
        "{%0,%1,%2,%3}, {%4,%5,%6,%7}, {%8,%9}, {%0,%1,%2,%3};"
        : "+r"(c[0]), "+r"(c[1]), "+r"(c[2]), "+r"(c[3])
        : "r"(a[0]), "r"(a[1]), "r"(a[2]), "r"(a[3]), "r"(b[0]), "r"(b[1]));
}

// ---------------- kernel 1: |W| partial sums (deterministic) ----------------
__global__ void k_absmean1(const float4* __restrict__ w4) {
    __shared__ float red[256];
    const int tid = threadIdx.x;
    const int gid = blockIdx.x * 256 + tid;
    float s = 0.f;
    for (int i = gid; i < (NN * KK / 4); i += 1024 * 256) {
        float4 v = w4[i];
        s += fabsf(v.x) + fabsf(v.y) + fabsf(v.z) + fabsf(v.w);
    }
    red[tid] = s;
    __syncthreads();
    for (int o = 128; o > 0; o >>= 1) {
        if (tid < o) red[tid] += red[tid + o];
        __syncthreads();
    }
    if (tid == 0) g_partial[blockIdx.x] = red[0];
}

// ---------------- kernel 2: finalize scale ----------------
__global__ void k_absmean2() {
    __shared__ float red[256];
    const int tid = threadIdx.x;
    float s = g_partial[tid] + g_partial[tid + 256] + g_partial[tid + 512] + g_partial[tid + 768];
    red[tid] = s;
    __syncthreads();
    for (int o = 128; o > 0; o >>= 1) {
        if (tid < o) red[tid] += red[tid + o];
        __syncthreads();
    }
    if (tid == 0) g_scale = fmaxf(red[0] * (1.f / 4194304.f), EPSV);  // /2^22 exact
}

// ---------------- kernel 3: quantize weights to ternary int8 ----------------
__global__ void k_quant_w(const float4* __restrict__ w4) {
    const int i = blockIdx.x * 256 + threadIdx.x;     // 0..1048575
    const float s = g_scale;
    float4 v = w4[i];
    float q0 = fminf(fmaxf(rintf(v.x / s), -1.f), 1.f);
    float q1 = fminf(fmaxf(rintf(v.y / s), -1.f), 1.f);
    float q2 = fminf(fmaxf(rintf(v.z / s), -1.f), 1.f);
    float q3 = fminf(fmaxf(rintf(v.w / s), -1.f), 1.f);
    char4 o;
    o.x = (char)(int)q0; o.y = (char)(int)q1; o.z = (char)(int)q2; o.w = (char)(int)q3;
    ((char4*)g_qw)[i] = o;
}

// ---------------- kernel 4: per-token activation quantization ----------------
__global__ void k_quant_x(const float* __restrict__ x) {
    __shared__ float red[256];
    __shared__ float s_qs;
    const int m = blockIdx.x;
    const int tid = threadIdx.x;
    const float4* row = (const float4*)(x + (size_t)m * KK);
    float4 a = row[tid];
    float4 b = row[tid + 256];
    float mx = fmaxf(fmaxf(fmaxf(fabsf(a.x), fabsf(a.y)), fmaxf(fabsf(a.z), fabsf(a.w))),
                     fmaxf(fmaxf(fabsf(b.x), fabsf(b.y)), fmaxf(fabsf(b.z), fabsf(b.w))));
    red[tid] = mx;
    __syncthreads();
    for (int o = 128; o > 0; o >>= 1) {
        if (tid < o) red[tid] = fmaxf(red[tid], red[tid + o]);
        __syncthreads();
    }
    if (tid == 0) {
        float gamma = fmaxf(red[0], EPSV);
        s_qs = 128.f / gamma;                          // Q/gamma, then multiply (matches ref)
        g_rowscale[m] = g_scale * gamma * 0.0078125f;  // scale*gamma/128 (exact shift)
    }
    __syncthreads();
    const float qs = s_qs;
    char4* orow = (char4*)(g_qx + (size_t)m * KK);
    char4 oa, ob;
    oa.x = (char)(int)fminf(fmaxf(rintf(a.x * qs), -128.f), 127.f);
    oa.y = (char)(int)fminf(fmaxf(rintf(a.y * qs), -128.f), 127.f);
    oa.z = (char)(int)fminf(fmaxf(rintf(a.z * qs), -128.f), 127.f);
    oa.w = (char)(int)fminf(fmaxf(rintf(a.w * qs), -128.f), 127.f);
    ob.x = (char)(int)fminf(fmaxf(rintf(b.x * qs), -128.f), 127.f);
    ob.y = (char)(int)fminf(fmaxf(rintf(b.y * qs), -128.f), 127.f);
    ob.z = (char)(int)fminf(fmaxf(rintf(b.z * qs), -128.f), 127.f);
    ob.w = (char)(int)fminf(fmaxf(rintf(b.w * qs), -128.f), 127.f);
    orow[tid] = oa;
    orow[tid + 256] = ob;
}

// ---------------- kernel 5: int8 mma.sync GEMM ----------------
// CTA tile 128(M) x 128(N), ktile = 64, 8 warps (warp tile 64x32), 2-stage cp.async.
// Smem row pitch 80B => conflict-free fragment loads (bank = 20*row + word mod 32).
#define KTILE 64
#define PITCH 80
#define TILE_BYTES (128 * PITCH)          // 10240 per operand
#define STG_BYTES (2 * TILE_BYTES)        // 20480 per stage (A then B)
#define NKT (KK / KTILE)                  // 32

__global__ void __launch_bounds__(256, 2) k_gemm(const float* __restrict__ bias,
                                                 float* __restrict__ out) {
    __shared__ alignas(16) char smem[2 * STG_BYTES];   // 40960 B
    const int tid = threadIdx.x;
    const int wid = tid >> 5, lane = tid & 31;
    const int grp = lane >> 2, tig = lane & 3;
    const int warp_m = wid >> 2, warp_n = wid & 3;     // 2 x 4 warp grid
    const int n0 = blockIdx.x * 128;
    const int m0 = blockIdx.y * 128;
    const uint32_t sb = smem_u32(smem);

    // per-thread cp.async chunk coords: chunks tid and tid+256 of 512 (row = c>>2, w16 = c&3)
    const int lrow = tid >> 2;          // 0..63
    const int lw = tid & 3;             // 16B word within 64B k-slab

    const int8_t* gA = g_qx + (size_t)m0 * KK;
    const int8_t* gB = g_qw + (size_t)n0 * KK;

    int acc[4][4][4];
#pragma unroll
    for (int i = 0; i < 4; ++i)
#pragma unroll
        for (int j = 0; j < 4; ++j)
#pragma unroll
            for (int r = 0; r < 4; ++r) acc[i][j][r] = 0;

    // ---- issue stage for ktile kt into buffer s ----
    auto issue = [&](int s, int kt) {
        const uint32_t dA = sb + s * STG_BYTES;
        const uint32_t dB = dA + TILE_BYTES;
        const int kb = kt * KTILE + lw * 16;
        cp16(dA + lrow * PITCH + lw * 16,        gA + (size_t)lrow * KK + kb);
        cp16(dA + (lrow + 64) * PITCH + lw * 16, gA + (size_t)(lrow + 64) * KK + kb);
        cp16(dB + lrow * PITCH + lw * 16,        gB + (size_t)lrow * KK + kb);
        cp16(dB + (lrow + 64) * PITCH + lw * 16, gB + (size_t)(lrow + 64) * KK + kb);
    };

    issue(0, 0);
    asm volatile("cp.async.commit_group;" ::: "memory");

    for (int kt = 0; kt < NKT; ++kt) {
        __syncthreads();  // previous compute done before overwriting other buffer
        if (kt + 1 < NKT) issue((kt + 1) & 1, kt + 1);
        asm volatile("cp.async.commit_group;" ::: "memory");
        asm volatile("cp.async.wait_group 1;" ::: "memory");
        __syncthreads();

        const uint32_t sA = sb + (kt & 1) * STG_BYTES;
        const uint32_t sB = sA + TILE_BYTES;
        const uint32_t aBase = sA + (uint32_t)(warp_m * 64 + grp) * PITCH + tig * 4;
        const uint32_t bBase = sB + (uint32_t)(warp_n * 32 + grp) * PITCH + tig * 4;

#pragma unroll
        for (int ks = 0; ks < 2; ++ks) {
            const uint32_t ko = ks * 32;
            uint32_t a[4][4], b[4][2];
#pragma unroll
            for (int i = 0; i < 4; ++i) {
                a[i][0] = lds32(aBase + (uint32_t)(i * 16) * PITCH + ko);
                a[i][1] = lds32(aBase + (uint32_t)(i * 16 + 8) * PITCH + ko);
                a[i][2] = lds32(aBase + (uint32_t)(i * 16) * PITCH + ko + 16);
                a[i][3] = lds32(aBase + (uint32_t)(i * 16 + 8) * PITCH + ko + 16);
            }
#pragma unroll
            for (int j = 0; j < 4; ++j) {
                b[j][0] = lds32(bBase + (uint32_t)(j * 8) * PITCH + ko);
                b[j][1] = lds32(bBase + (uint32_t)(j * 8) * PITCH + ko + 16);
            }
#pragma unroll
            for (int i = 0; i < 4; ++i)
#pragma unroll
                for (int j = 0; j < 4; ++j) mma_s8(acc[i][j], a[i], b[j]);
        }
    }

    // ---- epilogue: y = (dot + bias) * scale*gamma/128 ----
#pragma unroll
    for (int i = 0; i < 4; ++i) {
        const int R0 = m0 + warp_m * 64 + i * 16 + grp;
        const float rs0 = g_rowscale[R0];
        const float rs1 = g_rowscale[R0 + 8];
#pragma unroll
        for (int j = 0; j < 4; ++j) {
            const int col = n0 + warp_n * 32 + j * 8 + tig * 2;
            const float b0 = __ldg(&bias[col]);
            const float b1 = __ldg(&bias[col + 1]);
            float2 o0, o1;
            o0.x = ((float)acc[i][j][0] + b0) * rs0;
            o0.y = ((float)acc[i][j][1] + b1) * rs0;
            o1.x = ((float)acc[i][j][2] + b0) * rs1;
            o1.y = ((float)acc[i][j][3] + b1) * rs1;
            *(float2*)(out + (size_t)R0 * NN + col) = o0;
            *(float2*)(out + (size_t)(R0 + 8) * NN + col) = o1;
        }
    }
}

// ---------------- launcher ----------------
extern "C" void kernel_launch(void* const* d_in, const int* in_sizes, int n_in,
                              void* d_out, int out_size) {
    const float* x = nullptr;
    const float* w = nullptr;
    const float* b = nullptr;
    for (int i = 0; i < n_in; ++i) {
        if (in_sizes[i] == MM * KK) x = (const float*)d_in[i];
        else if (in_sizes[i] == NN * KK) w = (const float*)d_in[i];
        else if (in_sizes[i] == NN) b = (const float*)d_in[i];
    }
    (void)out_size;

    k_absmean1<<<1024, 256>>>((const float4*)w);
    k_absmean2<<<1, 256>>>();
    k_quant_w<<<4096, 256>>>((const float4*)w);
    k_quant_x<<<MM, 256>>>(x);
    k_gemm<<<dim3(NN / 128, MM / 128), 256>>>(b, (float*)d_out);
}

// round 3
// speedup vs baseline: 1.0667x; 1.0667x over previous
#include <cuda_runtime.h>
#include <cstdint>
#include <cstddef>

#define EPSV 1e-5f
#define MM 8192
#define KK 2048
#define NN 2048

// ---------------- scratch (device globals: no runtime allocation) ----------------
__device__ int8_t g_qx[(size_t)MM * KK];   // 16 MB quantized activations
__device__ int8_t g_qw[(size_t)NN * KK];   // 4 MB ternary weights
__device__ float g_rowscale[MM];
__device__ float g_partial[1024];
__device__ float g_scale;

// ---------------- helpers ----------------
__device__ __forceinline__ uint32_t smem_u32(const void* p) {
    uint32_t a;
    asm("{ .reg .u64 t; cvta.to.shared.u64 t, %1; cvt.u32.u64 %0, t; }" : "=r"(a) : "l"(p));
    return a;
}

__device__ __forceinline__ void cp16(uint32_t dst, const void* src) {
    asm volatile("cp.async.cg.shared.global [%0], [%1], 16;" :: "r"(dst), "l"(src) : "memory");
}

__device__ __forceinline__ void ldsm4(uint32_t& r0, uint32_t& r1, uint32_t& r2, uint32_t& r3,
                                      uint32_t addr) {
    asm volatile("ldmatrix.sync.aligned.m8n8.x4.shared.b16 {%0,%1,%2,%3}, [%4];"
                 : "=r"(r0), "=r"(r1), "=r"(r2), "=r"(r3) : "r"(addr));
}

__device__ __forceinline__ void mma_s8(int* c, const uint32_t* a, const uint32_t* b) {
    asm volatile(
        "mma.sync.aligned.m16n8k32.row.col.s32.s8.s8.s32 "
        "{%0,%1,%2,%3}, {%4,%5,%6,%7}, {%8,%9}, {%0,%1,%2,%3};"
        : "+r"(c[0]), "+r"(c[1]), "+r"(c[2]), "+r"(c[3])
        : "r"(a[0]), "r"(a[1]), "r"(a[2]), "r"(a[3]), "r"(b[0]), "r"(b[1]));
}

// ---------------- kernel 1: |W| partial sums (deterministic) ----------------
__global__ void k_absmean1(const float4* __restrict__ w4) {
    __shared__ float red[256];
    const int tid = threadIdx.x;
    const int gid = blockIdx.x * 256 + tid;
    float s = 0.f;
    for (int i = gid; i < (NN * KK / 4); i += 1024 * 256) {
        float4 v = w4[i];
        s += fabsf(v.x) + fabsf(v.y) + fabsf(v.z) + fabsf(v.w);
    }
    red[tid] = s;
    __syncthreads();
    for (int o = 128; o > 0; o >>= 1) {
        if (tid < o) red[tid] += red[tid + o];
        __syncthreads();
    }
    if (tid == 0) g_partial[blockIdx.x] = red[0];
}

// ---------------- kernel 2: finalize scale ----------------
__global__ void k_absmean2() {
    __shared__ float red[256];
    const int tid = threadIdx.x;
    float s = g_partial[tid] + g_partial[tid + 256] + g_partial[tid + 512] + g_partial[tid + 768];
    red[tid] = s;
    __syncthreads();
    for (int o = 128; o > 0; o >>= 1) {
        if (tid < o) red[tid] += red[tid + o];
        __syncthreads();
    }
    if (tid == 0) g_scale = fmaxf(red[0] * (1.f / 4194304.f), EPSV);  // /2^22 exact
}

// ---------------- kernel 3: quantize weights to ternary int8 ----------------
__global__ void k_quant_w(const float4* __restrict__ w4) {
    const int i = blockIdx.x * 256 + threadIdx.x;     // 0..1048575
    const float s = g_scale;
    float4 v = w4[i];
    float q0 = fminf(fmaxf(rintf(v.x / s), -1.f), 1.f);
    float q1 = fminf(fmaxf(rintf(v.y / s), -1.f), 1.f);
    float q2 = fminf(fmaxf(rintf(v.z / s), -1.f), 1.f);
    float q3 = fminf(fmaxf(rintf(v.w / s), -1.f), 1.f);
    char4 o;
    o.x = (char)(int)q0; o.y = (char)(int)q1; o.z = (char)(int)q2; o.w = (char)(int)q3;
    ((char4*)g_qw)[i] = o;
}

// ---------------- kernel 4: per-token activation quantization ----------------
__global__ void k_quant_x(const float* __restrict__ x) {
    __shared__ float red[8];
    const int m = blockIdx.x;
    const int tid = threadIdx.x;
    const int lane = tid & 31, w = tid >> 5;
    const float4* row = (const float4*)(x + (size_t)m * KK);
    float4 a = row[tid];
    float4 b = row[tid + 256];
    float mx = fmaxf(fmaxf(fmaxf(fabsf(a.x), fabsf(a.y)), fmaxf(fabsf(a.z), fabsf(a.w))),
                     fmaxf(fmaxf(fabsf(b.x), fabsf(b.y)), fmaxf(fabsf(b.z), fabsf(b.w))));
#pragma unroll
    for (int o = 16; o > 0; o >>= 1) mx = fmaxf(mx, __shfl_xor_sync(0xffffffffu, mx, o));
    if (lane == 0) red[w] = mx;
    __syncthreads();
    float g = red[0];
#pragma unroll
    for (int k = 1; k < 8; ++k) g = fmaxf(g, red[k]);
    const float gamma = fmaxf(g, EPSV);
    const float qs = 128.f / gamma;                       // Q/gamma, then multiply (matches ref)
    if (tid == 0) g_rowscale[m] = g_scale * gamma * 0.0078125f;  // scale*gamma/128 (exact)

    char4* orow = (char4*)(g_qx + (size_t)m * KK);
    char4 oa, ob;
    oa.x = (char)(int)fminf(fmaxf(rintf(a.x * qs), -128.f), 127.f);
    oa.y = (char)(int)fminf(fmaxf(rintf(a.y * qs), -128.f), 127.f);
    oa.z = (char)(int)fminf(fmaxf(rintf(a.z * qs), -128.f), 127.f);
    oa.w = (char)(int)fminf(fmaxf(rintf(a.w * qs), -128.f), 127.f);
    ob.x = (char)(int)fminf(fmaxf(rintf(b.x * qs), -128.f), 127.f);
    ob.y = (char)(int)fminf(fmaxf(rintf(b.y * qs), -128.f), 127.f);
    ob.z = (char)(int)fminf(fmaxf(rintf(b.z * qs), -128.f), 127.f);
    ob.w = (char)(int)fminf(fmaxf(rintf(b.w * qs), -128.f), 127.f);
    orow[tid] = oa;
    orow[tid + 256] = ob;
}

// ---------------- kernel 5: int8 mma.sync GEMM ----------------
// CTA tile 128(M) x 128(N), ktile = 64, 8 warps (warp tile 64x32),
// 4-stage cp.async pipeline, ONE __syncthreads per ktile, ldmatrix.x4 fragment loads.
// Smem row pitch 80B: ldmatrix 8-row x 16B matrices hit all 32 banks (conflict-free).
#define KTILE 64
#define PITCH 80
#define TILE_BYTES (128 * PITCH)          // 10240 per operand
#define STG_BYTES (2 * TILE_BYTES)        // 20480 per stage (A then B)
#define STAGES 4
#define NKT (KK / KTILE)                  // 32

__global__ void __launch_bounds__(256, 2) k_gemm(const float* __restrict__ bias,
                                                 float* __restrict__ out) {
    extern __shared__ char smem[];        // STAGES * STG_BYTES = 81920 B (dynamic)
    const int tid = threadIdx.x;
    const int wid = tid >> 5, lane = tid & 31;
    const int grp = lane >> 2, tig = lane & 3;
    const int warp_m = wid >> 2, warp_n = wid & 3;     // 2 x 4 warp grid
    const int n0 = blockIdx.x * 128;
    const int m0 = blockIdx.y * 128;
    const uint32_t sb = smem_u32(smem);

    // cp.async per-thread coords: 4 chunks of 16B each (A 2 rows + B 2 rows)
    const int lrow = tid >> 2;          // 0..63
    const int lw = tid & 3;             // 16B word within 64B k-slab

    const int8_t* gA = g_qx + (size_t)m0 * KK;
    const int8_t* gB = g_qw + (size_t)n0 * KK;

    // ldmatrix per-lane addresses (fragment layout proof in header comment)
    const uint32_t aOff = (uint32_t)(warp_m * 64 + (lane & 15)) * PITCH + ((lane >> 4) << 4);
    const uint32_t bOff = (uint32_t)(warp_n * 32 + ((lane >> 4) << 3) + (lane & 7)) * PITCH
                        + (((lane >> 3) & 1) << 4);

    int acc[4][4][4];
#pragma unroll
    for (int i = 0; i < 4; ++i)
#pragma unroll
        for (int j = 0; j < 4; ++j)
#pragma unroll
            for (int r = 0; r < 4; ++r) acc[i][j][r] = 0;

    auto issue = [&](int s, int kt) {
        const uint32_t dA = sb + s * STG_BYTES;
        const uint32_t dB = dA + TILE_BYTES;
        const int kb = kt * KTILE + lw * 16;
        cp16(dA + lrow * PITCH + lw * 16,        gA + (size_t)lrow * KK + kb);
        cp16(dA + (lrow + 64) * PITCH + lw * 16, gA + (size_t)(lrow + 64) * KK + kb);
        cp16(dB + lrow * PITCH + lw * 16,        gB + (size_t)lrow * KK + kb);
        cp16(dB + (lrow + 64) * PITCH + lw * 16, gB + (size_t)(lrow + 64) * KK + kb);
    };

#pragma unroll
    for (int s = 0; s < STAGES - 1; ++s) {
        issue(s, s);
        asm volatile("cp.async.commit_group;" ::: "memory");
    }

    for (int kt = 0; kt < NKT; ++kt) {
        asm volatile("cp.async.wait_group %0;" :: "n"(STAGES - 2) : "memory");
        __syncthreads();
        if (kt + STAGES - 1 < NKT) issue((kt + STAGES - 1) & (STAGES - 1), kt + STAGES - 1);
        asm volatile("cp.async.commit_group;" ::: "memory");

        const uint32_t sA = sb + (kt & (STAGES - 1)) * STG_BYTES;
        const uint32_t sB = sA + TILE_BYTES;

#pragma unroll
        for (int ks = 0; ks < 2; ++ks) {
            const uint32_t ko = ks * 32;
            uint32_t a[4][4], b[4][2];
#pragma unroll
            for (int i = 0; i < 4; ++i)
                ldsm4(a[i][0], a[i][1], a[i][2], a[i][3],
                      sA + aOff + (uint32_t)(i * 16) * PITCH + ko);
#pragma unroll
            for (int p = 0; p < 2; ++p)
                ldsm4(b[2 * p][0], b[2 * p][1], b[2 * p + 1][0], b[2 * p + 1][1],
                      sB + bOff + (uint32_t)(p * 16) * PITCH + ko);
#pragma unroll
            for (int i = 0; i < 4; ++i)
#pragma unroll
                for (int j = 0; j < 4; ++j) mma_s8(acc[i][j], a[i], b[j]);
        }
    }

    // ---- epilogue: y = (dot + bias) * scale*gamma/128 ----
#pragma unroll
    for (int i = 0; i < 4; ++i) {
        const int R0 = m0 + warp_m * 64 + i * 16 + grp;
        const float rs0 = g_rowscale[R0];
        const float rs1 = g_rowscale[R0 + 8];
#pragma unroll
        for (int j = 0; j < 4; ++j) {
            const int col = n0 + warp_n * 32 + j * 8 + tig * 2;
            const float b0 = __ldg(&bias[col]);
            const float b1 = __ldg(&bias[col + 1]);
            float2 o0, o1;
            o0.x = ((float)acc[i][j][0] + b0) * rs0;
            o0.y = ((float)acc[i][j][1] + b1) * rs0;
            o1.x = ((float)acc[i][j][2] + b0) * rs1;
            o1.y = ((float)acc[i][j][3] + b1) * rs1;
            *(float2*)(out + (size_t)R0 * NN + col) = o0;
            *(float2*)(out + (size_t)(R0 + 8) * NN + col) = o1;
        }
    }
}

// ---------------- launcher ----------------
extern "C" void kernel_launch(void* const* d_in, const int* in_sizes, int n_in,
                              void* d_out, int out_size) {
    const float* x = nullptr;
    const float* w = nullptr;
    const float* b = nullptr;
    for (int i = 0; i < n_in; ++i) {
        if (in_sizes[i] == MM * KK) x = (const float*)d_in[i];
        else if (in_sizes[i] == NN * KK) w = (const float*)d_in[i];
        else if (in_sizes[i] == NN) b = (const float*)d_in[i];
    }
    (void)out_size;

    cudaFuncSetAttribute(k_gemm, cudaFuncAttributeMaxDynamicSharedMemorySize,
                         STAGES * STG_BYTES);

    k_absmean1<<<1024, 256>>>((const float4*)w);
    k_absmean2<<<1, 256>>>();
    k_quant_w<<<4096, 256>>>((const float4*)w);
    k_quant_x<<<MM, 256>>>(x);
    k_gemm<<<dim3(NN / 128, MM / 128), 256, STAGES * STG_BYTES>>>(b, (float*)d_out);
}

// round 5
// speedup vs baseline: 1.0931x; 1.0248x over previous
#include <cuda_runtime.h>
#include <cstdint>
#include <cstddef>

#define EPSV 1e-5f
#define MM 8192
#define KK 2048
#define NN 2048

// ---------------- scratch (device globals: no runtime allocation) ----------------
__device__ int8_t g_qx[(size_t)MM * KK];   // 16 MB quantized activations
__device__ int8_t g_qw[(size_t)NN * KK];   // 4 MB ternary weights
__device__ float g_rowscale[MM];
__device__ float g_partial[1024];
__device__ float g_scale;
__device__ unsigned g_count = 0;

// ---------------- helpers ----------------
__device__ __forceinline__ uint32_t smem_u32(const void* p) {
    uint32_t a;
    asm("{ .reg .u64 t; cvta.to.shared.u64 t, %1; cvt.u32.u64 %0, t; }" : "=r"(a) : "l"(p));
    return a;
}

__device__ __forceinline__ void cp16(uint32_t dst, const void* src) {
    asm volatile("cp.async.cg.shared.global [%0], [%1], 16;" :: "r"(dst), "l"(src) : "memory");
}

__device__ __forceinline__ void ldsm4(uint32_t& r0, uint32_t& r1, uint32_t& r2, uint32_t& r3,
                                      uint32_t addr) {
    asm volatile("ldmatrix.sync.aligned.m8n8.x4.shared.b16 {%0,%1,%2,%3}, [%4];"
                 : "=r"(r0), "=r"(r1), "=r"(r2), "=r"(r3) : "r"(addr));
}

__device__ __forceinline__ void mma_s8(int* c, const uint32_t* a, const uint32_t* b) {
    asm volatile(
        "mma.sync.aligned.m16n8k32.row.col.s32.s8.s8.s32 "
        "{%0,%1,%2,%3}, {%4,%5,%6,%7}, {%8,%9}, {%0,%1,%2,%3};"
        : "+r"(c[0]), "+r"(c[1]), "+r"(c[2]), "+r"(c[3])
        : "r"(a[0]), "r"(a[1]), "r"(a[2]), "r"(a[3]), "r"(b[0]), "r"(b[1]));
}

// pack 4 rounded floats -> bytes {q3,q2,q1,q0} (q0 = lowest address), sat to [-128,127]
// cvt.pack.sat.s8.s32.b32 d,a,b,c computes d = (c<<16) | (sat8(a)<<8) | sat8(b)
__device__ __forceinline__ uint32_t quad_s8(float f0, float f1, float f2, float f3,
                                            float qs) {
    int q0 = __float2int_rn(f0 * qs);
    int q1 = __float2int_rn(f1 * qs);
    int q2 = __float2int_rn(f2 * qs);
    int q3 = __float2int_rn(f3 * qs);
    uint32_t hi, r;
    asm("cvt.pack.sat.s8.s32.b32 %0, %1, %2, 0;" : "=r"(hi) : "r"(q3), "r"(q2));
    asm("cvt.pack.sat.s8.s32.b32 %0, %1, %2, %3;" : "=r"(r) : "r"(q1), "r"(q0), "r"(hi));
    return r;
}

// ---------------- kernel 1: |W| absmean -> g_scale (fused final reduce) ----------------
__global__ void k_absmean(const float4* __restrict__ w4) {
    __shared__ float red[256];
    __shared__ unsigned isLast;
    const int tid = threadIdx.x;
    const int gid = blockIdx.x * 256 + tid;
    float s = 0.f;
    for (int i = gid; i < (NN * KK / 4); i += 1024 * 256) {
        float4 v = w4[i];
        s += fabsf(v.x) + fabsf(v.y) + fabsf(v.z) + fabsf(v.w);
    }
    red[tid] = s;
    __syncthreads();
    for (int o = 128; o > 0; o >>= 1) {
        if (tid < o) red[tid] += red[tid + o];
        __syncthreads();
    }
    if (tid == 0) {
        g_partial[blockIdx.x] = red[0];
        __threadfence();
        isLast = (atomicAdd(&g_count, 1u) == 1023u);
    }
    __syncthreads();
    if (isLast) {
        float t = g_partial[tid] + g_partial[tid + 256] + g_partial[tid + 512]
                + g_partial[tid + 768];
        red[tid] = t;
        __syncthreads();
        for (int o = 128; o > 0; o >>= 1) {
            if (tid < o) red[tid] += red[tid + o];
            __syncthreads();
        }
        if (tid == 0) {
            g_scale = fmaxf(red[0] * (1.f / 4194304.f), EPSV);  // /2^22 exact
            g_count = 0;   // reset for next graph replay
        }
    }
}

// ---------------- kernel 2: quantize weights to ternary int8 ----------------
__global__ void k_quant_w(const float4* __restrict__ w4) {
    const int i = blockIdx.x * 256 + threadIdx.x;     // 0..1048575
    const float s = g_scale;
    float4 v = w4[i];
    float q0 = fminf(fmaxf(rintf(v.x / s), -1.f), 1.f);
    float q1 = fminf(fmaxf(rintf(v.y / s), -1.f), 1.f);
    float q2 = fminf(fmaxf(rintf(v.z / s), -1.f), 1.f);
    float q3 = fminf(fmaxf(rintf(v.w / s), -1.f), 1.f);
    char4 o;
    o.x = (char)(int)q0; o.y = (char)(int)q1; o.z = (char)(int)q2; o.w = (char)(int)q3;
    ((char4*)g_qw)[i] = o;
}

// ---------------- kernel 3: per-token activation quantization (warp per row) ----------------
__global__ void __launch_bounds__(256) k_quant_x(const float* __restrict__ x) {
    const int lane = threadIdx.x & 31;
    const int m = blockIdx.x * 8 + (threadIdx.x >> 5);
    const float4* row = (const float4*)(x + (size_t)m * KK);

    float4 v[16];
#pragma unroll
    for (int i = 0; i < 16; ++i) v[i] = row[lane + 32 * i];

    float mx = 0.f;
#pragma unroll
    for (int i = 0; i < 16; ++i) {
        mx = fmaxf(mx, fmaxf(fmaxf(fabsf(v[i].x), fabsf(v[i].y)),
                             fmaxf(fabsf(v[i].z), fabsf(v[i].w))));
    }
#pragma unroll
    for (int o = 16; o > 0; o >>= 1) mx = fmaxf(mx, __shfl_xor_sync(0xffffffffu, mx, o));

    const float gamma = fmaxf(mx, EPSV);
    const float qs = 128.f / gamma;                      // Q/gamma then multiply (matches ref)
    if (lane == 0) g_rowscale[m] = g_scale * gamma * 0.0078125f;  // scale*gamma/128 exact

    uint32_t* orow = (uint32_t*)(g_qx + (size_t)m * KK);
#pragma unroll
    for (int i = 0; i < 16; ++i)
        orow[lane + 32 * i] = quad_s8(v[i].x, v[i].y, v[i].z, v[i].w, qs);
}

// ---------------- kernel 4: int8 mma.sync GEMM ----------------
// CTA tile 128(M) x 128(N), ktile = 64, 8 warps (warp tile 64x32),
// 4-stage cp.async pipeline, ONE __syncthreads per ktile, ldmatrix.x4 fragment loads.
// Smem row pitch 80B: ldmatrix 8-row x 16B matrices hit all 32 banks (conflict-free).
#define KTILE 64
#define PITCH 80
#define TILE_BYTES (128 * PITCH)          // 10240 per operand
#define STG_BYTES (2 * TILE_BYTES)        // 20480 per stage (A then B)
#define STAGES 4
#define NKT (KK / KTILE)                  // 32

__global__ void __launch_bounds__(256, 2) k_gemm(const float* __restrict__ bias,
                                                 float* __restrict__ out) {
    extern __shared__ char smem[];        // STAGES * STG_BYTES = 81920 B (dynamic)
    const int tid = threadIdx.x;
    const int wid = tid >> 5, lane = tid & 31;
    const int grp = lane >> 2, tig = lane & 3;
    const int warp_m = wid >> 2, warp_n = wid & 3;     // 2 x 4 warp grid
    const int n0 = blockIdx.x * 128;
    const int m0 = blockIdx.y * 128;
    const uint32_t sb = smem_u32(smem);

    const int lrow = tid >> 2;          // 0..63
    const int lw = tid & 3;             // 16B word within 64B k-slab

    const int8_t* gA = g_qx + (size_t)m0 * KK;
    const int8_t* gB = g_qw + (size_t)n0 * KK;

    const uint32_t aOff = (uint32_t)(warp_m * 64 + (lane & 15)) * PITCH + ((lane >> 4) << 4);
    const uint32_t bOff = (uint32_t)(warp_n * 32 + ((lane >> 4) << 3) + (lane & 7)) * PITCH
                        + (((lane >> 3) & 1) << 4);

    int acc[4][4][4];
#pragma unroll
    for (int i = 0; i < 4; ++i)
#pragma unroll
        for (int j = 0; j < 4; ++j)
#pragma unroll
            for (int r = 0; r < 4; ++r) acc[i][j][r] = 0;

    auto issue = [&](int s, int kt) {
        const uint32_t dA = sb + s * STG_BYTES;
        const uint32_t dB = dA + TILE_BYTES;
        const int kb = kt * KTILE + lw * 16;
        cp16(dA + lrow * PITCH + lw * 16,        gA + (size_t)lrow * KK + kb);
        cp16(dA + (lrow + 64) * PITCH + lw * 16, gA + (size_t)(lrow + 64) * KK + kb);
        cp16(dB + lrow * PITCH + lw * 16,        gB + (size_t)lrow * KK + kb);
        cp16(dB + (lrow + 64) * PITCH + lw * 16, gB + (size_t)(lrow + 64) * KK + kb);
    };

#pragma unroll
    for (int s = 0; s < STAGES - 1; ++s) {
        issue(s, s);
        asm volatile("cp.async.commit_group;" ::: "memory");
    }

    for (int kt = 0; kt < NKT; ++kt) {
        asm volatile("cp.async.wait_group %0;" :: "n"(STAGES - 2) : "memory");
        __syncthreads();
        if (kt + STAGES - 1 < NKT) issue((kt + STAGES - 1) & (STAGES - 1), kt + STAGES - 1);
        asm volatile("cp.async.commit_group;" ::: "memory");

        const uint32_t sA = sb + (kt & (STAGES - 1)) * STG_BYTES;
        const uint32_t sB = sA + TILE_BYTES;

#pragma unroll
        for (int ks = 0; ks < 2; ++ks) {
            const uint32_t ko = ks * 32;
            uint32_t a[4][4], b[4][2];
#pragma unroll
            for (int i = 0; i < 4; ++i)
                ldsm4(a[i][0], a[i][1], a[i][2], a[i][3],
                      sA + aOff + (uint32_t)(i * 16) * PITCH + ko);
#pragma unroll
            for (int p = 0; p < 2; ++p)
                ldsm4(b[2 * p][0], b[2 * p][1], b[2 * p + 1][0], b[2 * p + 1][1],
                      sB + bOff + (uint32_t)(p * 16) * PITCH + ko);
#pragma unroll
            for (int i = 0; i < 4; ++i)
#pragma unroll
                for (int j = 0; j < 4; ++j) mma_s8(acc[i][j], a[i], b[j]);
        }
    }

    // ---- epilogue: y = (dot + bias) * scale*gamma/128 ----
#pragma unroll
    for (int i = 0; i < 4; ++i) {
        const int R0 = m0 + warp_m * 64 + i * 16 + grp;
        const float rs0 = g_rowscale[R0];
        const float rs1 = g_rowscale[R0 + 8];
#pragma unroll
        for (int j = 0; j < 4; ++j) {
            const int col = n0 + warp_n * 32 + j * 8 + tig * 2;
            const float b0 = __ldg(&bias[col]);
            const float b1 = __ldg(&bias[col + 1]);
            float2 o0, o1;
            o0.x = ((float)acc[i][j][0] + b0) * rs0;
            o0.y = ((float)acc[i][j][1] + b1) * rs0;
            o1.x = ((float)acc[i][j][2] + b0) * rs1;
            o1.y = ((float)acc[i][j][3] + b1) * rs1;
            *(float2*)(out + (size_t)R0 * NN + col) = o0;
            *(float2*)(out + (size_t)(R0 + 8) * NN + col) = o1;
        }
    }
}

// ---------------- launcher ----------------
extern "C" void kernel_launch(void* const* d_in, const int* in_sizes, int n_in,
                              void* d_out, int out_size) {
    const float* x = nullptr;
    const float* w = nullptr;
    const float* b = nullptr;
    for (int i = 0; i < n_in; ++i) {
        if (in_sizes[i] == MM * KK) x = (const float*)d_in[i];
        else if (in_sizes[i] == NN * KK) w = (const float*)d_in[i];
        else if (in_sizes[i] == NN) b = (const float*)d_in[i];
    }
    (void)out_size;

    cudaFuncSetAttribute(k_gemm, cudaFuncAttributeMaxDynamicSharedMemorySize,
                         STAGES * STG_BYTES);

    k_absmean<<<1024, 256>>>((const float4*)w);
    k_quant_w<<<4096, 256>>>((const float4*)w);
    k_quant_x<<<1024, 256>>>(x);
    k_gemm<<<dim3(NN / 128, MM / 128), 256, STAGES * STG_BYTES>>>(b, (float*)d_out);
}